// round 3
// baseline (speedup 1.0000x reference)
#include <cuda_runtime.h>

typedef unsigned long long ull;
#define PAD 132

// ---- f32x2 packed helpers ----
__device__ __forceinline__ ull pack2(float x, float y) {
    ull r; asm("mov.b64 %0, {%1,%2};" : "=l"(r) : "f"(x), "f"(y)); return r;
}
__device__ __forceinline__ void unpack2(ull v, float& x, float& y) {
    asm("mov.b64 {%0,%1}, %2;" : "=f"(x), "=f"(y) : "l"(v));
}
__device__ __forceinline__ ull fma2(ull a, ull b, ull c) {
    ull d; asm("fma.rn.f32x2 %0, %1, %2, %3;" : "=l"(d) : "l"(a), "l"(b), "l"(c)); return d;
}
__device__ __forceinline__ ull add2(ull a, ull b) {
    ull d; asm("add.rn.f32x2 %0, %1, %2;" : "=l"(d) : "l"(a), "l"(b)); return d;
}

// Mask dtype auto-detect: 0 = int32, 1 = uint8, 2 = float32
__device__ __forceinline__ bool mask_at(const void* p, int i, int mode) {
    if (mode == 0) return ((const int*)p)[i] != 0;
    if (mode == 2) return ((const float*)p)[i] != 0.0f;
    return ((const unsigned char*)p)[i] != 0;
}

// ============================================================================
// Fully fused kernel. grid = 128 = (batch b, n-half). 256 threads.
// Block owns output rows n in [32*half, 32*half+32) x all m of batch b.
//  1. zero-fill own output window
//  2. ballot-compact q-window mask (<=32 rows) and full d-mask (<=64 rows)
//  3. hq = Xq[valid] @ W1[:128] + b1  -> smem   (W1 q-half staged in smem)
//  4. hd = Xd[valid] @ W1[128:]      -> smem   (same W buffer reloaded)
//  5. pairwise: relu(hq+hd) @ W2 + b2 for valid pairs only, 2x2 f32x2 tiles
// Nothing round-trips through global between phases.
// ============================================================================
__global__ void __launch_bounds__(256, 1)
fused_kernel(const float* __restrict__ query, const float* __restrict__ doc,
             const void* __restrict__ qmask, const void* __restrict__ dmask,
             const float* __restrict__ W1, const float* __restrict__ b1,
             const float* __restrict__ W2g, const float* __restrict__ b2g,
             float* __restrict__ out)
{
    extern __shared__ float sm[];
    float* Ws   = sm;                   // [128][PAD]  W1 half (reused q->d)
    float* Xs   = Ws + 128 * PAD;       // [64][PAD]   staged X rows (reused)
    float* hq_s = Xs + 64 * PAD;        // [32][PAD]
    float* hd_s = hq_s + 32 * PAD;      // [64][PAD]
    float* w2_s = hd_s + 64 * PAD;      // [3][128]
    float* b1s  = w2_s + 384;           // [128]
    int* nlist  = (int*)(b1s + 128);    // 34 (local n within window)
    int* mlist  = nlist + 34;           // 66 (global m)
    int* meta   = mlist + 66;           // [0]=notInt [1]=notF32 [2]=nvh [3]=mv

    const int tid  = threadIdx.x;
    const int lane = tid & 31;
    const int wid  = tid >> 5;
    const int b    = blockIdx.x >> 1;
    const int half = blockIdx.x & 1;

    if (tid < 4) meta[tid] = 0;
    __syncthreads();

    // ---- mask dtype detection (scan 512 words; valid under every candidate)
    {
        const unsigned* qw = (const unsigned*)qmask;
        int notInt = 0, notF32 = 0;
        for (int i = tid; i < 512; i += 256) {
            unsigned w = qw[i];
            if (w > 1u) notInt = 1;
            if (w != 0u && w != 0x3F800000u) notF32 = 1;
        }
        if (notInt) meta[0] = 1;
        if (notF32) meta[1] = 1;
    }

    // ---- zero-fill own output window (overlaps with everything below)
    float* obase = out + (size_t)(b * 64 + half * 32) * 64 * 3;
    {
        float4 z = make_float4(0.f, 0.f, 0.f, 0.f);
        for (int i = tid; i < 32 * 64 * 3 / 4; i += 256)
            ((float4*)obase)[i] = z;
    }
    __syncthreads();
    const int mode = (meta[0] == 0) ? 0 : ((meta[1] == 0) ? 2 : 1);

    // ---- ballot compaction + W2/b1 staging (per-warp roles)
    if (wid == 0) {
        bool v = mask_at(qmask, b * 64 + half * 32 + lane, mode);
        unsigned mm = __ballot_sync(0xFFFFFFFFu, v);
        unsigned lt = (1u << lane) - 1u;
        if (v) nlist[__popc(mm & lt)] = lane;
        if (lane == 0) {
            int c = __popc(mm);
            meta[2] = c;
            if (c & 1) nlist[c] = 31 - __clz(mm);   // pad with dup of last valid
        }
    } else if (wid == 1) {
        bool v0 = mask_at(dmask, b * 64 + lane, mode);
        unsigned m0 = __ballot_sync(0xFFFFFFFFu, v0);
        bool v1 = mask_at(dmask, b * 64 + 32 + lane, mode);
        unsigned m1 = __ballot_sync(0xFFFFFFFFu, v1);
        unsigned lt = (1u << lane) - 1u;
        int c0 = __popc(m0);
        if (v0) mlist[__popc(m0 & lt)] = lane;
        if (v1) mlist[c0 + __popc(m1 & lt)] = 32 + lane;
        if (lane == 0) {
            int c = c0 + __popc(m1);
            meta[3] = c;
            if (c & 1) mlist[c] = m1 ? (32 + 31 - __clz(m1)) : (31 - __clz(m0));
        }
    } else if (wid < 4) {
        for (int i = tid - 64; i < 384; i += 64) {  // W2 (128,3) -> [o][h]
            int h = i / 3, o = i - h * 3;
            w2_s[o * 128 + h] = W2g[i];
        }
    } else if (wid == 4) {
        for (int i = lane; i < 128; i += 32) b1s[i] = b1[i];
    }

    // ---- stage W1 q-half [128][PAD] (all threads)
    for (int i = tid; i < 128 * 32; i += 256)
        *(float4*)(Ws + (i >> 5) * PAD + (i & 31) * 4) = ((const float4*)W1)[i];
    __syncthreads();

    const int nvh = meta[2], mv = meta[3];
    const int nvhp = (nvh + 1) & ~1;
    const int mvp  = (mv + 1) & ~1;

    // ---- stage compacted Xq rows (row-major, broadcast-friendly)
    const float* Xq = query + (size_t)b * 64 * 128;
    for (int i = tid; i < nvhp * 32; i += 256) {
        int r = i >> 5, seg = i & 31;
        *(float4*)(Xs + r * PAD + seg * 4) =
            ((const float4*)(Xq + (half * 32 + nlist[r]) * 128))[seg];
    }
    __syncthreads();

    // ---- hq = Xq @ W1q + b1  (thread = 1 row x 16 h; <=32*8=256 jobs)
    {
        const int r = tid >> 3, hgrp = tid & 7, h0 = hgrp * 16;
        if (r < nvhp) {
            ull acc[8];
#pragma unroll
            for (int j = 0; j < 8; j++) acc[j] = 0ull;
            const float* xb = Xs + r * PAD;
            const float* wb = Ws + h0;
#pragma unroll 4
            for (int d = 0; d < 128; d++) {
                float x = xb[d];
                ull xp = pack2(x, x);
                const ulonglong2* wr = (const ulonglong2*)(wb + d * PAD);
                ulonglong2 wa = wr[0], wb2 = wr[1], wc = wr[2], wd = wr[3];
                acc[0] = fma2(xp, wa.x,  acc[0]);
                acc[1] = fma2(xp, wa.y,  acc[1]);
                acc[2] = fma2(xp, wb2.x, acc[2]);
                acc[3] = fma2(xp, wb2.y, acc[3]);
                acc[4] = fma2(xp, wc.x,  acc[4]);
                acc[5] = fma2(xp, wc.y,  acc[5]);
                acc[6] = fma2(xp, wd.x,  acc[6]);
                acc[7] = fma2(xp, wd.y,  acc[7]);
            }
            float v[16];
#pragma unroll
            for (int j = 0; j < 8; j++) unpack2(acc[j], v[2 * j], v[2 * j + 1]);
#pragma unroll
            for (int k = 0; k < 16; k++) v[k] += b1s[h0 + k];
            float* go = hq_s + r * PAD + h0;
#pragma unroll
            for (int q = 0; q < 4; q++)
                *(float4*)(go + q * 4) =
                    make_float4(v[4 * q], v[4 * q + 1], v[4 * q + 2], v[4 * q + 3]);
        }
    }
    __syncthreads();

    // ---- reload Ws with W1 d-half; stage compacted Xd rows
    for (int i = tid; i < 128 * 32; i += 256)
        *(float4*)(Ws + (i >> 5) * PAD + (i & 31) * 4) =
            ((const float4*)(W1 + 128 * 128))[i];
    const float* Xd = doc + (size_t)b * 64 * 128;
    for (int i = tid; i < mvp * 32; i += 256) {
        int r = i >> 5, seg = i & 31;
        *(float4*)(Xs + r * PAD + seg * 4) =
            ((const float4*)(Xd + mlist[r] * 128))[seg];
    }
    __syncthreads();

    // ---- hd = Xd @ W1d  (<=64*8=512 jobs, 2 per thread)
    {
        const int hgrp = tid & 7, h0 = hgrp * 16;
        for (int r = tid >> 3; r < mvp; r += 32) {
            ull acc[8];
#pragma unroll
            for (int j = 0; j < 8; j++) acc[j] = 0ull;
            const float* xb = Xs + r * PAD;
            const float* wb = Ws + h0;
#pragma unroll 4
            for (int d = 0; d < 128; d++) {
                float x = xb[d];
                ull xp = pack2(x, x);
                const ulonglong2* wr = (const ulonglong2*)(wb + d * PAD);
                ulonglong2 wa = wr[0], wb2 = wr[1], wc = wr[2], wd = wr[3];
                acc[0] = fma2(xp, wa.x,  acc[0]);
                acc[1] = fma2(xp, wa.y,  acc[1]);
                acc[2] = fma2(xp, wb2.x, acc[2]);
                acc[3] = fma2(xp, wb2.y, acc[3]);
                acc[4] = fma2(xp, wc.x,  acc[4]);
                acc[5] = fma2(xp, wc.y,  acc[5]);
                acc[6] = fma2(xp, wd.x,  acc[6]);
                acc[7] = fma2(xp, wd.y,  acc[7]);
            }
            float* go = hd_s + r * PAD + h0;
#pragma unroll
            for (int j = 0; j < 4; j++) {
                float a, b2, c, d2;
                unpack2(acc[2 * j],     a, b2);
                unpack2(acc[2 * j + 1], c, d2);
                *(float4*)(go + j * 4) = make_float4(a, b2, c, d2);
            }
        }
    }
    __syncthreads();

    // ---- pairwise scores, 2n x 2m tiles, valid pairs only
    if (nvh == 0 || mv == 0) return;
    const float b2_0 = b2g[0], b2_1 = b2g[1], b2_2 = b2g[2];
    const int ntiles = nvhp >> 1, mtiles = mvp >> 1;
    const int total = ntiles * mtiles;

    for (int t = tid; t < total; t += 256) {
        int ni = t / mtiles;
        int mi = t - ni * mtiles;
        const float* pa0 = hq_s + (2 * ni) * PAD;
        const float* pa1 = pa0 + PAD;
        const float* pd0 = hd_s + (2 * mi) * PAD;
        const float* pd1 = pd0 + PAD;

        ull acc[4][3];
#pragma unroll
        for (int c = 0; c < 4; c++)
#pragma unroll
            for (int o = 0; o < 3; o++) acc[c][o] = 0ull;

#define COMBO(c, Alo, Ahi, Dlo, Dhi) do {                                   \
            ull tlo = add2((Alo), (Dlo));                                    \
            ull thi = add2((Ahi), (Dhi));                                    \
            float f0, f1, f2, f3;                                            \
            unpack2(tlo, f0, f1); unpack2(thi, f2, f3);                      \
            f0 = fmaxf(f0, 0.f); f1 = fmaxf(f1, 0.f);                        \
            f2 = fmaxf(f2, 0.f); f3 = fmaxf(f3, 0.f);                        \
            tlo = pack2(f0, f1); thi = pack2(f2, f3);                        \
            acc[c][0] = fma2(tlo, w0.x, acc[c][0]);                          \
            acc[c][0] = fma2(thi, w0.y, acc[c][0]);                          \
            acc[c][1] = fma2(tlo, w1.x, acc[c][1]);                          \
            acc[c][1] = fma2(thi, w1.y, acc[c][1]);                          \
            acc[c][2] = fma2(tlo, w2v.x, acc[c][2]);                         \
            acc[c][2] = fma2(thi, w2v.y, acc[c][2]);                         \
        } while (0)

#pragma unroll 4
        for (int h = 0; h < 128; h += 4) {
            ulonglong2 A0 = *(const ulonglong2*)(pa0 + h);
            ulonglong2 A1 = *(const ulonglong2*)(pa1 + h);
            ulonglong2 D0 = *(const ulonglong2*)(pd0 + h);
            ulonglong2 D1 = *(const ulonglong2*)(pd1 + h);
            ulonglong2 w0  = *(const ulonglong2*)(w2_s + h);
            ulonglong2 w1  = *(const ulonglong2*)(w2_s + 128 + h);
            ulonglong2 w2v = *(const ulonglong2*)(w2_s + 256 + h);
            COMBO(0, A0.x, A0.y, D0.x, D0.y);
            COMBO(1, A0.x, A0.y, D1.x, D1.y);
            COMBO(2, A1.x, A1.y, D0.x, D0.y);
            COMBO(3, A1.x, A1.y, D1.x, D1.y);
        }
#undef COMBO

        const int gn0 = nlist[2 * ni], gn1 = nlist[2 * ni + 1];
        const int gm0 = mlist[2 * mi], gm1 = mlist[2 * mi + 1];

#define WRITE(c, gn, gm) do {                                               \
            float lo, hi, s0, s1, s2;                                        \
            unpack2(acc[c][0], lo, hi); s0 = lo + hi + b2_0;                 \
            unpack2(acc[c][1], lo, hi); s1 = lo + hi + b2_1;                 \
            unpack2(acc[c][2], lo, hi); s2 = lo + hi + b2_2;                 \
            float* po = obase + ((gn) * 64 + (gm)) * 3;                      \
            po[0] = s0; po[1] = s1; po[2] = s2;                              \
        } while (0)

        WRITE(0, gn0, gm0);
        WRITE(1, gn0, gm1);
        WRITE(2, gn1, gm0);
        WRITE(3, gn1, gm1);
#undef WRITE
    }
}

// ============================================================================
extern "C" void kernel_launch(void* const* d_in, const int* in_sizes, int n_in,
                              void* d_out, int out_size)
{
    const float* query = (const float*)d_in[0];
    const float* doc   = (const float*)d_in[1];
    const void*  qmask = d_in[2];
    const void*  dmask = d_in[3];
    const float* W1    = (const float*)d_in[4];
    const float* b1    = (const float*)d_in[5];
    const float* W2    = (const float*)d_in[6];
    const float* b2    = (const float*)d_in[7];
    float* out = (float*)d_out;

    const int smem = (128 * PAD + 64 * PAD + 32 * PAD + 64 * PAD + 384 + 128)
                         * (int)sizeof(float)
                     + (34 + 66 + 4) * (int)sizeof(int);   // ~151 KB

    cudaFuncSetAttribute(fused_kernel,
                         cudaFuncAttributeMaxDynamicSharedMemorySize, smem);

    fused_kernel<<<128, 256, smem>>>(query, doc, qmask, dmask, W1, b1, W2, b2, out);
}

// round 6
// speedup vs baseline: 2.9978x; 2.9978x over previous
#include <cuda_runtime.h>

typedef unsigned long long ull;
#define WPAD 132   // row stride (floats) for Ws / hq_s / hd_s
#define XROW 132   // row stride for staged X rows (128 data + 4 pad)

// ---- f32x2 packed helpers ----
__device__ __forceinline__ ull pack2(float x, float y) {
    ull r; asm("mov.b64 %0, {%1,%2};" : "=l"(r) : "f"(x), "f"(y)); return r;
}
__device__ __forceinline__ void unpack2(ull v, float& x, float& y) {
    asm("mov.b64 {%0,%1}, %2;" : "=f"(x), "=f"(y) : "l"(v));
}
__device__ __forceinline__ ull fma2(ull a, ull b, ull c) {
    ull d; asm("fma.rn.f32x2 %0, %1, %2, %3;" : "=l"(d) : "l"(a), "l"(b), "l"(c)); return d;
}
__device__ __forceinline__ ull add2(ull a, ull b) {
    ull d; asm("add.rn.f32x2 %0, %1, %2;" : "=l"(d) : "l"(a), "l"(b)); return d;
}

// Mask dtype auto-detect: 0 = int32, 1 = uint8, 2 = float32
__device__ __forceinline__ bool mask_at(const void* p, int i, int mode) {
    if (mode == 0) return ((const int*)p)[i] != 0;
    if (mode == 2) return ((const float*)p)[i] != 0.0f;
    return ((const unsigned char*)p)[i] != 0;
}

// ============================================================================
// Fused kernel. grid = 128 = (batch b, n-half). 256 threads.
// All inner loops conflict-free; every compute phase fma-pipe bound.
// ============================================================================
__global__ void __launch_bounds__(256, 1)
fused_kernel(const float* __restrict__ query, const float* __restrict__ doc,
             const void* __restrict__ qmask, const void* __restrict__ dmask,
             const float* __restrict__ W1, const float* __restrict__ b1,
             const float* __restrict__ W2g, const float* __restrict__ b2g,
             float* __restrict__ out)
{
    extern __shared__ float sm[];
    float* Ws   = sm;                   // [128][WPAD]  W1 half (q then d)
    float* Xs   = Ws + 128 * WPAD;      // [64][XROW]   staged X rows
    float* hq_s = Xs + 64 * XROW;       // [32][WPAD]
    float* hd_s = hq_s + 32 * WPAD;     // [64][WPAD]
    float* w2_s = hd_s + 64 * WPAD;     // [3][128]
    float* b1s  = w2_s + 384;           // [128]
    int* nlist  = (int*)(b1s + 128);    // 34 (local n in window)
    int* mlist  = nlist + 34;           // 66 (global m)
    int* meta   = mlist + 66;           // [0]=notInt [1]=notF32 [2]=nvh [3]=mv

    const int tid  = threadIdx.x;
    const int lane = tid & 31;
    const int wid  = tid >> 5;
    const int b    = blockIdx.x >> 1;
    const int half = blockIdx.x & 1;

    if (tid < 4) meta[tid] = 0;
    __syncthreads();

    // ---- mask dtype detection + zero-fill own output window
    {
        const unsigned* qw = (const unsigned*)qmask;
        int notInt = 0, notF32 = 0;
        for (int i = tid; i < 512; i += 256) {
            unsigned w = qw[i];
            notInt |= (w > 1u) ? 1 : 0;
            notF32 |= (w != 0u && w != 0x3F800000u) ? 1 : 0;
        }
        if (notInt) meta[0] = 1;
        if (notF32) meta[1] = 1;
    }
    float* obase = out + (size_t)(b * 64 + half * 32) * 192;  // 32n x 64m x 3
    {
        float4 z = make_float4(0.f, 0.f, 0.f, 0.f);
        for (int i = tid; i < 1536; i += 256) ((float4*)obase)[i] = z;
    }
    __syncthreads();
    const int mode = (meta[0] == 0) ? 0 : ((meta[1] == 0) ? 2 : 1);

    // ---- per-warp roles: ballots / W2 transpose / b1
    if (wid == 0) {
        bool v = mask_at(qmask, b * 64 + half * 32 + lane, mode);
        unsigned mm = __ballot_sync(0xFFFFFFFFu, v);
        unsigned lt = (1u << lane) - 1u;
        if (v) nlist[__popc(mm & lt)] = lane;
        if (lane == 0) {
            int c = __popc(mm);
            meta[2] = c;
            if (c & 1) nlist[c] = 31 - __clz(mm);        // pad dup of last valid
        }
    } else if (wid == 1) {
        bool v0 = mask_at(dmask, b * 64 + lane, mode);
        unsigned m0 = __ballot_sync(0xFFFFFFFFu, v0);
        bool v1 = mask_at(dmask, b * 64 + 32 + lane, mode);
        unsigned m1 = __ballot_sync(0xFFFFFFFFu, v1);
        unsigned lt = (1u << lane) - 1u;
        int c0 = __popc(m0);
        if (v0) mlist[__popc(m0 & lt)] = lane;
        if (v1) mlist[c0 + __popc(m1 & lt)] = 32 + lane;
        if (lane == 0) {
            int c = c0 + __popc(m1);
            meta[3] = c;
            if (c & 1) mlist[c] = m1 ? (32 + 31 - __clz(m1)) : (31 - __clz(m0));
        }
    } else if (wid == 2 || wid == 3) {
        for (int i = tid - 64; i < 384; i += 64) {       // W2 (128,3) -> [o][h]
            int h = i / 3, o = i - h * 3;
            w2_s[o * 128 + h] = W2g[i];
        }
    } else if (wid == 4) {
        for (int i = lane; i < 128; i += 32) b1s[i] = b1[i];
    }

    // ---- stage W1 q-half (all threads)
    for (int i = tid; i < 4096; i += 256)
        *(float4*)(Ws + (i >> 5) * WPAD + (i & 31) * 4) = ((const float4*)W1)[i];
    __syncthreads();

    const int nvh = meta[2], mv = meta[3];
    const int nvhp = (nvh + 1) & ~1;
    const int mvp  = (mv + 1) & ~1;

    // ---- stage compacted Xq rows (row-major, stride XROW)
    const float* Xq = query + (size_t)b * 8192;
    for (int i = tid; i < nvhp * 32; i += 256) {
        int r = i >> 5, seg = i & 31;
        *(float4*)(Xs + r * XROW + seg * 4) =
            ((const float4*)(Xq + (half * 32 + nlist[r]) * 128))[seg];
    }
    __syncthreads();

    // thread h-mapping shared by hq/hd: 16 h-groups of 8, bank-rotated chunks
    const int hgrp = tid & 15;
    const int h0   = hgrp * 8;
    const int cj   = (hgrp >> 2) & 1;
    const int o0   = h0 + 4 * cj;          // first 4-float chunk this thread loads
    const int o1   = h0 + 4 * (cj ^ 1);    // second chunk
    const int grp  = tid >> 4;             // 0..15 row group

    // ---- hq: 2 rows x 8 h per thread
    {
        const int r0 = 2 * grp;
        if (r0 < nvhp) {
            ull a0=0,a1=0,a2=0,a3=0,a4=0,a5=0,a6=0,a7=0;
            const float* x0  = Xs + r0 * XROW;
            const float* x1  = x0 + XROW;
            const float* wp0 = Ws + o0;
            const float* wp1 = Ws + o1;
#pragma unroll 4
            for (int d = 0; d < 128; d++) {
                float xa = x0[d], xb = x1[d];
                ull pa = pack2(xa, xa), pb = pack2(xb, xb);
                ulonglong2 wA = *(const ulonglong2*)(wp0 + d * WPAD);
                ulonglong2 wB = *(const ulonglong2*)(wp1 + d * WPAD);
                a0 = fma2(pa, wA.x, a0); a1 = fma2(pa, wA.y, a1);
                a2 = fma2(pa, wB.x, a2); a3 = fma2(pa, wB.y, a3);
                a4 = fma2(pb, wA.x, a4); a5 = fma2(pb, wA.y, a5);
                a6 = fma2(pb, wB.x, a6); a7 = fma2(pb, wB.y, a7);
            }
            float v[8];
            float4 s;
            unpack2(a0, v[0], v[1]); unpack2(a1, v[2], v[3]);
            s = make_float4(v[0] + b1s[o0], v[1] + b1s[o0+1],
                            v[2] + b1s[o0+2], v[3] + b1s[o0+3]);
            *(float4*)(hq_s + r0 * WPAD + o0) = s;
            unpack2(a2, v[4], v[5]); unpack2(a3, v[6], v[7]);
            s = make_float4(v[4] + b1s[o1], v[5] + b1s[o1+1],
                            v[6] + b1s[o1+2], v[7] + b1s[o1+3]);
            *(float4*)(hq_s + r0 * WPAD + o1) = s;
            unpack2(a4, v[0], v[1]); unpack2(a5, v[2], v[3]);
            s = make_float4(v[0] + b1s[o0], v[1] + b1s[o0+1],
                            v[2] + b1s[o0+2], v[3] + b1s[o0+3]);
            *(float4*)(hq_s + (r0+1) * WPAD + o0) = s;
            unpack2(a6, v[4], v[5]); unpack2(a7, v[6], v[7]);
            s = make_float4(v[4] + b1s[o1], v[5] + b1s[o1+1],
                            v[6] + b1s[o1+2], v[7] + b1s[o1+3]);
            *(float4*)(hq_s + (r0+1) * WPAD + o1) = s;
        }
    }
    __syncthreads();

    // ---- stage W1 d-half (overwrite) + compacted Xd rows
    for (int i = tid; i < 4096; i += 256)
        *(float4*)(Ws + (i >> 5) * WPAD + (i & 31) * 4) =
            ((const float4*)(W1 + 16384))[i];
    const float* Xd = doc + (size_t)b * 8192;
    for (int i = tid; i < mvp * 32; i += 256) {
        int r = i >> 5, seg = i & 31;
        *(float4*)(Xs + r * XROW + seg * 4) =
            ((const float4*)(Xd + mlist[r] * 128))[seg];
    }
    __syncthreads();

    // ---- hd: 4 rows x 8 h per thread (no bias)
    {
        const int r0 = 4 * grp;
        if (r0 < mvp) {
            ull ac[4][4];
#pragma unroll
            for (int r = 0; r < 4; r++)
#pragma unroll
                for (int j = 0; j < 4; j++) ac[r][j] = 0ull;
            const float* xb  = Xs + r0 * XROW;
            const float* wp0 = Ws + o0;
            const float* wp1 = Ws + o1;
#pragma unroll 4
            for (int d = 0; d < 128; d++) {
                ulonglong2 wA = *(const ulonglong2*)(wp0 + d * WPAD);
                ulonglong2 wB = *(const ulonglong2*)(wp1 + d * WPAD);
#pragma unroll
                for (int r = 0; r < 4; r++) {
                    float x = xb[r * XROW + d];
                    ull px = pack2(x, x);
                    ac[r][0] = fma2(px, wA.x, ac[r][0]);
                    ac[r][1] = fma2(px, wA.y, ac[r][1]);
                    ac[r][2] = fma2(px, wB.x, ac[r][2]);
                    ac[r][3] = fma2(px, wB.y, ac[r][3]);
                }
            }
#pragma unroll
            for (int r = 0; r < 4; r++) {
                if (r0 + r < mvp) {
                    float v[8];
                    unpack2(ac[r][0], v[0], v[1]); unpack2(ac[r][1], v[2], v[3]);
                    *(float4*)(hd_s + (r0+r) * WPAD + o0) =
                        make_float4(v[0], v[1], v[2], v[3]);
                    unpack2(ac[r][2], v[4], v[5]); unpack2(ac[r][3], v[6], v[7]);
                    *(float4*)(hd_s + (r0+r) * WPAD + o1) =
                        make_float4(v[4], v[5], v[6], v[7]);
                }
            }
        }
    }
    __syncthreads();

    // ---- pairwise: tiles pair rows (i, i+half-count) -> conflict-free LDS
    const int nt = nvhp >> 1, mt = mvp >> 1;
    const int total = nt * mt;
    const float b2_0 = b2g[0], b2_1 = b2g[1], b2_2 = b2g[2];

    for (int t = tid; t < total; t += 256) {
        int ni = t / mt;
        int mi = t - ni * mt;
        const float* pa0 = hq_s + ni * WPAD;
        const float* pa1 = hq_s + (ni + nt) * WPAD;
        const float* pd0 = hd_s + mi * WPAD;
        const float* pd1 = hd_s + (mi + mt) * WPAD;

        ull acc[4][3];
#pragma unroll
        for (int c = 0; c < 4; c++)
#pragma unroll
            for (int o = 0; o < 3; o++) acc[c][o] = 0ull;

#define COMBO(c, Alo, Ahi, Dlo, Dhi) do {                                   \
            ull tlo = add2((Alo), (Dlo));                                    \
            ull thi = add2((Ahi), (Dhi));                                    \
            float f0, f1, f2, f3;                                            \
            unpack2(tlo, f0, f1); unpack2(thi, f2, f3);                      \
            f0 = fmaxf(f0, 0.f); f1 = fmaxf(f1, 0.f);                        \
            f2 = fmaxf(f2, 0.f); f3 = fmaxf(f3, 0.f);                        \
            tlo = pack2(f0, f1); thi = pack2(f2, f3);                        \
            acc[c][0] = fma2(tlo, w0.x, acc[c][0]);                          \
            acc[c][0] = fma2(thi, w0.y, acc[c][0]);                          \
            acc[c][1] = fma2(tlo, w1.x, acc[c][1]);                          \
            acc[c][1] = fma2(thi, w1.y, acc[c][1]);                          \
            acc[c][2] = fma2(tlo, w2v.x, acc[c][2]);                         \
            acc[c][2] = fma2(thi, w2v.y, acc[c][2]);                         \
        } while (0)

#pragma unroll 4
        for (int h = 0; h < 128; h += 4) {
            ulonglong2 A0 = *(const ulonglong2*)(pa0 + h);
            ulonglong2 A1 = *(const ulonglong2*)(pa1 + h);
            ulonglong2 D0 = *(const ulonglong2*)(pd0 + h);
            ulonglong2 D1 = *(const ulonglong2*)(pd1 + h);
            ulonglong2 w0  = *(const ulonglong2*)(w2_s + h);
            ulonglong2 w1  = *(const ulonglong2*)(w2_s + 128 + h);
            ulonglong2 w2v = *(const ulonglong2*)(w2_s + 256 + h);
            COMBO(0, A0.x, A0.y, D0.x, D0.y);
            COMBO(1, A0.x, A0.y, D1.x, D1.y);
            COMBO(2, A1.x, A1.y, D0.x, D0.y);
            COMBO(3, A1.x, A1.y, D1.x, D1.y);
        }
#undef COMBO

        const int gn0 = nlist[ni],      gn1 = nlist[ni + nt];
        const int gm0 = mlist[mi],      gm1 = mlist[mi + mt];

#define WRITE(c, gn, gm) do {                                               \
            float lo, hi, s0, s1, s2;                                        \
            unpack2(acc[c][0], lo, hi); s0 = lo + hi + b2_0;                 \
            unpack2(acc[c][1], lo, hi); s1 = lo + hi + b2_1;                 \
            unpack2(acc[c][2], lo, hi); s2 = lo + hi + b2_2;                 \
            float* po = obase + ((gn) * 64 + (gm)) * 3;                      \
            po[0] = s0; po[1] = s1; po[2] = s2;                              \
        } while (0)

        WRITE(0, gn0, gm0);
        WRITE(1, gn0, gm1);
        WRITE(2, gn1, gm0);
        WRITE(3, gn1, gm1);
#undef WRITE
    }
}

// ============================================================================
extern "C" void kernel_launch(void* const* d_in, const int* in_sizes, int n_in,
                              void* d_out, int out_size)
{
    const float* query = (const float*)d_in[0];
    const float* doc   = (const float*)d_in[1];
    const void*  qmask = d_in[2];
    const void*  dmask = d_in[3];
    const float* W1    = (const float*)d_in[4];
    const float* b1    = (const float*)d_in[5];
    const float* W2    = (const float*)d_in[6];
    const float* b2    = (const float*)d_in[7];
    float* out = (float*)d_out;

    const int smem = (128 * WPAD + 64 * XROW + 32 * WPAD + 64 * WPAD + 384 + 128)
                         * (int)sizeof(float)
                     + (34 + 66 + 4) * (int)sizeof(int);   // ~156 KB

    cudaFuncSetAttribute(fused_kernel,
                         cudaFuncAttributeMaxDynamicSharedMemorySize, smem);

    fused_kernel<<<128, 256, smem>>>(query, doc, qmask, dmask, W1, b1, W2, b2, out);
}